// round 4
// baseline (speedup 1.0000x reference)
#include <cuda_runtime.h>
#include <cstdint>

#define BATCH 8
#define TLEN 64000
#define NFR 251
#define NB 513
#define NCH 32
#define NNODES 250
#define NODE_DIM 4116
#define SCC 20
#define EPSV 1e-5f

// ---------------- scratch (device globals; no allocation) ----------------
__device__ float g_s[BATCH * NB * NFR];
__device__ float2 g_tw[512];
__device__ float g_nodes[BATCH * NNODES * NODE_DIM];
__device__ float g_gh[BATCH * NNODES * 512];
__device__ float g_ssrc[BATCH * NNODES * 8];
__device__ float g_sdst[BATCH * NNODES * 8];
__device__ float g_g1[BATCH * NNODES * 512];
__device__ float g_h2g[BATCH * NNODES * 32];
__device__ float g_s2src[BATCH * NNODES];
__device__ float g_s2dst[BATCH * NNODES];
__device__ float g_g2[BATCH * NNODES * 32];

__device__ __forceinline__ uint32_t tf32r(float x) {
    uint32_t u;
    asm("cvt.rna.tf32.f32 %0, %1;" : "=r"(u) : "f"(x));
    return u;
}
__device__ __forceinline__ void mma_tf32(float* c,
                                         uint32_t a0, uint32_t a1, uint32_t a2, uint32_t a3,
                                         uint32_t b0, uint32_t b1) {
    asm volatile("mma.sync.aligned.m16n8k8.row.col.f32.tf32.tf32.f32 "
                 "{%0,%1,%2,%3},{%4,%5,%6,%7},{%8,%9},{%0,%1,%2,%3};"
                 : "+f"(c[0]), "+f"(c[1]), "+f"(c[2]), "+f"(c[3])
                 : "r"(a0), "r"(a1), "r"(a2), "r"(a3), "r"(b0), "r"(b1));
}

// ---------------- twiddle table init ----------------
__global__ void k_twinit() {
    int t = threadIdx.x;
    float ang = -6.283185307179586f * (float)t / 1024.f;
    float si, co;
    sincosf(ang, &si, &co);
    g_tw[t] = make_float2(co, si);
}

// ---------------- sinc conv (only first 1000 outputs needed) ----------------
__global__ void k_sinc(const float* __restrict__ x, const float* __restrict__ w) {
    __shared__ float sw[1024];
    __shared__ float sx[1536];
    int b = blockIdx.x / SCC, c = blockIdx.x % SCC;
    for (int i = threadIdx.x; i < 1024; i += 256) sw[i] = w[c * 1024 + i];
    for (int i = threadIdx.x; i < 1536; i += 256)
        sx[i] = (i < 1512) ? x[b * TLEN + i] : 0.f;
    __syncthreads();
    for (int t = threadIdx.x; t < NNODES; t += 256) {
        float acc = 0.f;
        for (int q = 0; q < 4; q++) {
            int p = 4 * t + q;
            int k0 = 512 - p; if (k0 < 0) k0 = 0;
            const float* xs = sx + p - 512;
            for (int k = k0; k < 1024; k++) acc = fmaf(sw[k], xs[k], acc);
        }
        g_nodes[(b * NNODES + t) * NODE_DIM + c] = acc * 0.25f;
    }
}

// ---------------- STFT: 1024-pt radix-2 FFT per frame (table twiddles) ------
__global__ void k_stft(const float* __restrict__ x) {
    __shared__ float re[1024], im[1024];
    __shared__ float2 tw[512];
    int b = blockIdx.x / NFR, fr = blockIdx.x % NFR;
    int base = fr * 256 - 512;
    int t = threadIdx.x;
    tw[t] = g_tw[t];
    for (int n = t; n < 1024; n += 512) {
        int m = base + n;
        if (m < 0) m = -m;
        else if (m >= TLEN) m = 2 * TLEN - 2 - m;
        int r = (int)(__brev((unsigned)n) >> 22);
        re[r] = x[b * TLEN + m];
        im[r] = 0.f;
    }
    __syncthreads();
    int mult = 512;
    for (int len = 2; len <= 1024; len <<= 1) {
        int half = len >> 1;
        int j = t & (half - 1);
        int pos = (t / half) * len + j;
        float2 wv = tw[j * mult];
        float co = wv.x, si = wv.y;
        float ur = re[pos], ui = im[pos];
        float vr = re[pos + half], vi = im[pos + half];
        float tr = vr * co - vi * si;
        float ti = vr * si + vi * co;
        re[pos] = ur + tr; im[pos] = ui + ti;
        re[pos + half] = ur - tr; im[pos + half] = ui - ti;
        mult >>= 1;
        __syncthreads();
    }
    for (int k = t; k <= 512; k += 512) {
        float mg = sqrtf(re[k] * re[k] + im[k] * im[k]);
        g_s[(b * NB + k) * NFR + fr] = logf(mg + 1e-9f);
    }
}

// ---------------- fused conv1 + tf32-MMA conv2 + 2x2 maxpool + scatter -------
// block 256 thr = 8 warps; tile 8 y-rows x 32 x-cols of conv2 output, 32 co.
// warp yy handles one output row: M=32 positions, N=32 co, K=288 (ci,ky,kx).
#define H1_STRIDE 36   // k-dim pad (bank-conflict-free fragments)
#define W2_STRIDE 36
__global__ void k_fused(const float* __restrict__ w1, const float* __restrict__ b1,
                        const float* __restrict__ g1v, const float* __restrict__ be1,
                        const float* __restrict__ w2, const float* __restrict__ b2,
                        const float* __restrict__ g2v, const float* __restrict__ be2) {
    extern __shared__ float smem[];
    uint32_t* h1t = (uint32_t*)smem;                 // [10][34][36] = 12240
    uint32_t* wt2 = (uint32_t*)(smem + 12240);       // [9][32][36] = 10368
    float* sst = smem + 12240 + 10368;               // [12][36] = 432
    float* w1s = sst + 432;                          // 288
    float* pm = smem;                                // reuse: [8][32][33] = 8448

    int x0 = blockIdx.x * 32, y0 = blockIdx.y * 8, b = blockIdx.z;
    int tid = threadIdx.x;

    // load conv2 weights -> [kyx][ci][co] tf32
    for (int i = tid; i < 9216; i += 256) {
        int co = i & 31; int rest = i >> 5;
        int ci = rest & 31; int kyx = rest >> 5;
        wt2[(kyx * 32 + ci) * W2_STRIDE + co] = tf32r(w2[(co * 32 + ci) * 9 + kyx]);
    }
    for (int i = tid; i < 288; i += 256) w1s[i] = w1[i];
    for (int i = tid; i < 12 * 36; i += 256) {
        int cc = i % 36, rr = i / 36;
        int gy = y0 - 2 + rr, gx = x0 - 2 + cc;
        float v = 0.f;
        if (gy >= 0 && gy < NB && gx >= 0 && gx < NFR)
            v = g_s[(b * NB + gy) * NFR + gx];
        sst[i] = v;
    }
    __syncthreads();

    // conv1 -> h1 tile [pos][ci] tf32 (warp per (rr,cc) pair, lane = ci)
    {
        int ci = tid & 31;
        float cb1 = b1[ci];
        float sc1 = g1v[ci] * rsqrtf(1.f + EPSV);
        float bb1 = be1[ci];
        const float* wp = w1s + ci * 9;
        for (int r = tid >> 5; r < 340; r += 8) {
            int cc = r % 34, rr = r / 34;
            int y = y0 - 1 + rr, xg = x0 - 1 + cc;
            float v = 0.f;
            if (y >= 0 && y < NB && xg >= 0 && xg < NFR) {
                float acc = cb1;
#pragma unroll
                for (int ky = 0; ky < 3; ky++)
#pragma unroll
                    for (int kx = 0; kx < 3; kx++)
                        acc = fmaf(wp[ky * 3 + kx], sst[(rr + ky) * 36 + (cc + kx)], acc);
                acc = acc * sc1 + bb1;
                v = acc > 0.f ? acc : 0.f;
            }
            h1t[(rr * 34 + cc) * H1_STRIDE + ci] = tf32r(v);
        }
    }
    __syncthreads();

    // conv2 main loop: implicit GEMM, tf32 mma
    int warp = tid >> 5, lane = tid & 31;
    int gid = lane >> 2, tig = lane & 3;
    int yy = warp;
    float c[2][4][4] = {};
    int abase = (yy * 34 + gid) * H1_STRIDE + tig;
    int bbase = tig * W2_STRIDE + gid;
#pragma unroll
    for (int ky = 0; ky < 3; ky++) {
#pragma unroll
        for (int kx = 0; kx < 3; kx++) {
            int kyx = ky * 3 + kx;
            int aoff0 = abase + (ky * 34 + kx) * H1_STRIDE;
            int boff0 = bbase + kyx * 32 * W2_STRIDE;
#pragma unroll
            for (int kc = 0; kc < 4; kc++) {
                uint32_t a[2][4], bf[4][2];
#pragma unroll
                for (int mt = 0; mt < 2; mt++) {
                    int ao = aoff0 + mt * 16 * H1_STRIDE + kc * 8;
                    a[mt][0] = h1t[ao];
                    a[mt][1] = h1t[ao + 8 * H1_STRIDE];
                    a[mt][2] = h1t[ao + 4];
                    a[mt][3] = h1t[ao + 8 * H1_STRIDE + 4];
                }
#pragma unroll
                for (int nt = 0; nt < 4; nt++) {
                    int bo = boff0 + kc * 8 * W2_STRIDE + nt * 8;
                    bf[nt][0] = wt2[bo];
                    bf[nt][1] = wt2[bo + 4 * W2_STRIDE];
                }
#pragma unroll
                for (int mt = 0; mt < 2; mt++)
#pragma unroll
                    for (int nt = 0; nt < 4; nt++)
                        mma_tf32(c[mt][nt], a[mt][0], a[mt][1], a[mt][2], a[mt][3],
                                 bf[nt][0], bf[nt][1]);
            }
        }
    }
    __syncthreads();   // h1t dead; pm reuses it

    // epilogue: bias + BN + ReLU -> pm[y][x][co]
    float rs = rsqrtf(1.f + EPSV);
#pragma unroll
    for (int nt = 0; nt < 4; nt++) {
        int co0 = nt * 8 + tig * 2;
        float cb0 = b2[co0], sc0 = g2v[co0] * rs, bb0 = be2[co0];
        float cb1v = b2[co0 + 1], sc1v = g2v[co0 + 1] * rs, bb1v = be2[co0 + 1];
#pragma unroll
        for (int mt = 0; mt < 2; mt++) {
            int xa = mt * 16 + gid;
            int xbp = xa + 8;
            float v0 = fmaxf((c[mt][nt][0] + cb0) * sc0 + bb0, 0.f);
            float v1 = fmaxf((c[mt][nt][1] + cb1v) * sc1v + bb1v, 0.f);
            float v2 = fmaxf((c[mt][nt][2] + cb0) * sc0 + bb0, 0.f);
            float v3 = fmaxf((c[mt][nt][3] + cb1v) * sc1v + bb1v, 0.f);
            pm[(yy * 32 + xa) * 33 + co0] = v0;
            pm[(yy * 32 + xa) * 33 + co0 + 1] = v1;
            pm[(yy * 32 + xbp) * 33 + co0] = v2;
            pm[(yy * 32 + xbp) * 33 + co0 + 1] = v3;
        }
    }
    __syncthreads();

    // 2x2 maxpool + scatter float4 (4 pooled rows) into g_nodes
    int co = tid & 31, txh = tid >> 5;
#pragma unroll
    for (int t2 = 0; t2 < 2; t2++) {
        int txp = txh * 2 + t2;
        int tp = (x0 >> 1) + txp;
        if (tp < 125) {
            float4 v;
#pragma unroll
            for (int fy = 0; fy < 4; fy++) {
                int yA = 2 * fy, yB = 2 * fy + 1;
                float m0 = fmaxf(pm[(yA * 32 + 2 * txp) * 33 + co],
                                 pm[(yA * 32 + 2 * txp + 1) * 33 + co]);
                float m1 = fmaxf(pm[(yB * 32 + 2 * txp) * 33 + co],
                                 pm[(yB * 32 + 2 * txp + 1) * 33 + co]);
                ((float*)&v)[fy] = fmaxf(m0, m1);
            }
            int t = 2 * tp + (co >> 4);
            long off = (long)(b * NNODES + t) * NODE_DIM + SCC + (co & 15) * 256 + (y0 >> 1);
            *(float4*)(g_nodes + off) = v;
        }
    }
}

// ---------------- gemm1 via split-tf32 (3-term) tensor cores -----------------
// C[2000,512] = nodes[2000,4116] @ W[4116,512]; 128x64 block tile, 8 warps 32x32
__global__ void k_gemm1_t(const float* __restrict__ Wg) {
    __shared__ uint32_t Ah[128 * 20], Al[128 * 20];
    __shared__ uint32_t Bh[16 * 72], Bl[16 * 72];
    const int M = BATCH * NNODES, N = 512, K = NODE_DIM;
    int bx = blockIdx.x, by = blockIdx.y;
    int tid = threadIdx.x;
    int warp = tid >> 5, lane = tid & 31;
    int gid = lane >> 2, tig = lane & 3;
    int wm = (warp >> 1) * 32, wn = (warp & 1) * 32;
    float c[2][4][4] = {};
    for (int k0 = 0; k0 < K; k0 += 16) {
        for (int i = tid; i < 2048; i += 256) {
            int m = i >> 4, kk = i & 15;
            int gm = by * 128 + m, gk = k0 + kk;
            float v = (gm < M && gk < K) ? g_nodes[(long)gm * K + gk] : 0.f;
            uint32_t hi = tf32r(v);
            Ah[m * 20 + kk] = hi;
            Al[m * 20 + kk] = tf32r(v - __uint_as_float(hi));
        }
        for (int i = tid; i < 1024; i += 256) {
            int kk = i >> 6, n = i & 63;
            int gk = k0 + kk;
            float v = (gk < K) ? Wg[(long)gk * N + bx * 64 + n] : 0.f;
            uint32_t hi = tf32r(v);
            Bh[kk * 72 + n] = hi;
            Bl[kk * 72 + n] = tf32r(v - __uint_as_float(hi));
        }
        __syncthreads();
#pragma unroll
        for (int ks = 0; ks < 16; ks += 8) {
            uint32_t ah[2][4], al[2][4], bh[4][2], bl[4][2];
#pragma unroll
            for (int mi = 0; mi < 2; mi++) {
                int mb = wm + mi * 16;
                int i0 = (mb + gid) * 20 + ks + tig;
                int i1 = (mb + gid + 8) * 20 + ks + tig;
                ah[mi][0] = Ah[i0]; ah[mi][1] = Ah[i1];
                ah[mi][2] = Ah[i0 + 4]; ah[mi][3] = Ah[i1 + 4];
                al[mi][0] = Al[i0]; al[mi][1] = Al[i1];
                al[mi][2] = Al[i0 + 4]; al[mi][3] = Al[i1 + 4];
            }
#pragma unroll
            for (int ni = 0; ni < 4; ni++) {
                int nb = wn + ni * 8;
                bh[ni][0] = Bh[(ks + tig) * 72 + nb + gid];
                bh[ni][1] = Bh[(ks + tig + 4) * 72 + nb + gid];
                bl[ni][0] = Bl[(ks + tig) * 72 + nb + gid];
                bl[ni][1] = Bl[(ks + tig + 4) * 72 + nb + gid];
            }
#pragma unroll
            for (int mi = 0; mi < 2; mi++)
#pragma unroll
                for (int ni = 0; ni < 4; ni++) {
                    mma_tf32(c[mi][ni], ah[mi][0], ah[mi][1], ah[mi][2], ah[mi][3],
                             bl[ni][0], bl[ni][1]);
                    mma_tf32(c[mi][ni], al[mi][0], al[mi][1], al[mi][2], al[mi][3],
                             bh[ni][0], bh[ni][1]);
                    mma_tf32(c[mi][ni], ah[mi][0], ah[mi][1], ah[mi][2], ah[mi][3],
                             bh[ni][0], bh[ni][1]);
                }
        }
        __syncthreads();
    }
#pragma unroll
    for (int mi = 0; mi < 2; mi++) {
        int r0 = by * 128 + wm + mi * 16 + gid;
        int r1 = r0 + 8;
#pragma unroll
        for (int ni = 0; ni < 4; ni++) {
            int gcol = bx * 64 + wn + ni * 8 + tig * 2;
            if (r0 < M) {
                float2 v = {c[mi][ni][0], c[mi][ni][1]};
                *(float2*)(g_gh + (long)r0 * N + gcol) = v;
            }
            if (r1 < M) {
                float2 v = {c[mi][ni][2], c[mi][ni][3]};
                *(float2*)(g_gh + (long)r1 * N + gcol) = v;
            }
        }
    }
}

// ---------------- generic tiled SGEMM (64x64x16) for gemm2 -------------------
__device__ __forceinline__ void gemm_body(const float* __restrict__ A,
                                          const float* __restrict__ B,
                                          float* __restrict__ C,
                                          int M, int N, int K) {
    __shared__ float As[16][65];
    __shared__ float Bs[16][64];
    int bx = blockIdx.x, by = blockIdx.y;
    int tid = threadIdx.x;
    int tr = tid >> 4, tc = tid & 15;
    float acc[4][4] = {};
    for (int k0 = 0; k0 < K; k0 += 16) {
        for (int i = tid; i < 64 * 16; i += 256) {
            int m = i >> 4, kk = i & 15;
            int gm = by * 64 + m, gk = k0 + kk;
            As[kk][m] = (gm < M && gk < K) ? A[(long)gm * K + gk] : 0.f;
        }
        for (int i = tid; i < 16 * 64; i += 256) {
            int kk = i >> 6, n = i & 63;
            int gk = k0 + kk, gn = bx * 64 + n;
            Bs[kk][n] = (gk < K && gn < N) ? B[(long)gk * N + gn] : 0.f;
        }
        __syncthreads();
#pragma unroll
        for (int kk = 0; kk < 16; kk++) {
            float a[4], bv[4];
#pragma unroll
            for (int i = 0; i < 4; i++) a[i] = As[kk][tr * 4 + i];
#pragma unroll
            for (int jq = 0; jq < 4; jq++) bv[jq] = Bs[kk][tc * 4 + jq];
#pragma unroll
            for (int i = 0; i < 4; i++)
#pragma unroll
                for (int jq = 0; jq < 4; jq++)
                    acc[i][jq] = fmaf(a[i], bv[jq], acc[i][jq]);
        }
        __syncthreads();
    }
    for (int i = 0; i < 4; i++) {
        int gm = by * 64 + tr * 4 + i;
        if (gm >= M) continue;
        for (int jq = 0; jq < 4; jq++) {
            int gn = bx * 64 + tc * 4 + jq;
            if (gn < N) C[(long)gm * N + gn] = acc[i][jq];
        }
    }
}
__global__ void k_gemm2(const float* __restrict__ W) {
    gemm_body(g_g1, W, g_h2g, BATCH * NNODES, 32, 512);
}

// ---------------- GAT1 attention scores ----------------
__global__ void k_scores1(const float* __restrict__ asrc, const float* __restrict__ adst) {
    int idx = blockIdx.x * 256 + threadIdx.x;
    if (idx >= BATCH * NNODES * 8) return;
    int h = idx & 7;
    int bn = idx >> 3;
    const float* hp = g_gh + (long)bn * 512 + h * 64;
    float s1 = 0.f, s2 = 0.f;
    for (int f = 0; f < 64; f++) {
        float v = hp[f];
        s1 = fmaf(v, asrc[h * 64 + f], s1);
        s2 = fmaf(v, adst[h * 64 + f], s2);
    }
    g_ssrc[idx] = s1;
    g_sdst[idx] = s2;
}

// ---------------- GAT1 softmax-attention + aggregate (10 i per block) --------
__global__ void k_att1(const float* __restrict__ bias) {
    extern __shared__ float sm[];
    float* swj = sm;               // [10][250][8] = 20000
    float* ss = sm + 20000;        // 2000
    float* sums = sm + 22000;      // 80
    int b = blockIdx.x / 25, ig = blockIdx.x % 25;
    int i0 = ig * 10;
    int tid = threadIdx.x;
    for (int i = tid; i < 2000; i += 256) ss[i] = g_ssrc[b * 2000 + i];
    __syncthreads();
    int warp = tid >> 5, lane = tid & 31;
    for (int task = warp; task < 80; task += 8) {
        int ii = task >> 3, h = task & 7;
        float d = g_sdst[(b * NNODES + i0 + ii) * 8 + h];
        float mx = -1e30f;
        for (int j = lane; j < NNODES; j += 32) {
            float e = d + ss[j * 8 + h];
            e = e > 0.f ? e : 0.2f * e;
            mx = fmaxf(mx, e);
        }
#pragma unroll
        for (int o = 16; o; o >>= 1) mx = fmaxf(mx, __shfl_xor_sync(0xffffffffu, mx, o));
        float smv = 0.f;
        for (int j = lane; j < NNODES; j += 32) {
            float e = d + ss[j * 8 + h];
            e = e > 0.f ? e : 0.2f * e;
            float wv = expf(e - mx);
            swj[(ii * NNODES + j) * 8 + h] = wv;
            smv += wv;
        }
#pragma unroll
        for (int o = 16; o; o >>= 1) smv += __shfl_xor_sync(0xffffffffu, smv, o);
        if (!lane) sums[ii * 8 + h] = smv;
    }
    __syncthreads();
    float acc0[10], acc1[10];
#pragma unroll
    for (int ii = 0; ii < 10; ii++) { acc0[ii] = 0.f; acc1[ii] = 0.f; }
    const float* Hb = g_gh + (long)b * NNODES * 512;
    int f0 = tid, f1 = tid + 256;
    int h0 = f0 >> 6, h1 = f1 >> 6;
    for (int j = 0; j < NNODES; j++) {
        float v0 = Hb[j * 512 + f0];
        float v1 = Hb[j * 512 + f1];
#pragma unroll
        for (int ii = 0; ii < 10; ii++) {
            acc0[ii] = fmaf(swj[(ii * NNODES + j) * 8 + h0], v0, acc0[ii]);
            acc1[ii] = fmaf(swj[(ii * NNODES + j) * 8 + h1], v1, acc1[ii]);
        }
    }
    float bi0 = bias[f0], bi1 = bias[f1];
    for (int ii = 0; ii < 10; ii++) {
        int i = i0 + ii;
        float* op = g_g1 + (long)(b * NNODES + i) * 512;
        float o0 = acc0[ii] / sums[ii * 8 + h0] + bi0;
        float o1 = acc1[ii] / sums[ii * 8 + h1] + bi1;
        op[f0] = o0 > 0.f ? o0 : 0.f;
        op[f1] = o1 > 0.f ? o1 : 0.f;
    }
}

// ---------------- GAT2 scores ----------------
__global__ void k_scores2(const float* __restrict__ asrc, const float* __restrict__ adst) {
    int idx = blockIdx.x * 256 + threadIdx.x;
    if (idx >= BATCH * NNODES) return;
    const float* hp = g_h2g + (long)idx * 32;
    float s1 = 0.f, s2 = 0.f;
    for (int f = 0; f < 32; f++) {
        float v = hp[f];
        s1 = fmaf(v, asrc[f], s1);
        s2 = fmaf(v, adst[f], s2);
    }
    g_s2src[idx] = s1;
    g_s2dst[idx] = s2;
}

// ---------------- GAT2 attention + aggregate ----------------
__global__ void k_att2(const float* __restrict__ bias) {
    __shared__ float sh[NNODES * 32];
    __shared__ float ssr[NNODES];
    __shared__ float wjs[8][NNODES];
    int b = blockIdx.x;
    int tid = threadIdx.x, warp = tid >> 5, lane = tid & 31;
    for (int i = tid; i < NNODES * 32; i += 256) sh[i] = g_h2g[b * NNODES * 32 + i];
    for (int i = tid; i < NNODES; i += 256) ssr[i] = g_s2src[b * NNODES + i];
    __syncthreads();
    float bi = bias[lane];
    for (int i = warp; i < NNODES; i += 8) {
        float d = g_s2dst[b * NNODES + i];
        float mx = -1e30f;
        for (int j = lane; j < NNODES; j += 32) {
            float e = d + ssr[j];
            e = e > 0.f ? e : 0.2f * e;
            mx = fmaxf(mx, e);
        }
#pragma unroll
        for (int o = 16; o; o >>= 1) mx = fmaxf(mx, __shfl_xor_sync(0xffffffffu, mx, o));
        float sum = 0.f;
        for (int j = lane; j < NNODES; j += 32) {
            float e = d + ssr[j];
            e = e > 0.f ? e : 0.2f * e;
            float wv = expf(e - mx);
            wjs[warp][j] = wv;
            sum += wv;
        }
#pragma unroll
        for (int o = 16; o; o >>= 1) sum += __shfl_xor_sync(0xffffffffu, sum, o);
        __syncwarp();
        float acc = 0.f;
        for (int j = 0; j < NNODES; j++) acc = fmaf(wjs[warp][j], sh[j * 32 + lane], acc);
        g_g2[(b * NNODES + i) * 32 + lane] = acc / sum + bi;
    }
}

// ---------------- mean-pool + FC head ----------------
__global__ void k_head(const float* __restrict__ fc1w, const float* __restrict__ fc1b,
                       const float* __restrict__ bg, const float* __restrict__ bb2,
                       const float* __restrict__ fc2w, const float* __restrict__ fc2b,
                       float* __restrict__ out, int write_emb) {
    __shared__ float semb[32];
    __shared__ float sz[128];
    int b = blockIdx.x, tid = threadIdx.x;
    if (tid < 32) {
        float s = 0.f;
        for (int i = 0; i < NNODES; i++) s += g_g2[(b * NNODES + i) * 32 + tid];
        s *= (1.f / 250.f);
        semb[tid] = s;
        if (write_emb) out[16 + b * 32 + tid] = s;
    }
    __syncthreads();
    {
        float z = fc1b[tid];
        for (int f = 0; f < 32; f++) z = fmaf(semb[f], fc1w[f * 128 + tid], z);
        z = z * (bg[tid] * rsqrtf(1.f + EPSV)) + bb2[tid];
        sz[tid] = z > 0.f ? z : 0.f;
    }
    __syncthreads();
    if (tid < 2) {
        float o = fc2b[tid];
        for (int q = 0; q < 128; q++) o = fmaf(sz[q], fc2w[q * 2 + tid], o);
        out[b * 2 + tid] = o;
    }
}

extern "C" void kernel_launch(void* const* d_in, const int* in_sizes, int n_in,
                              void* d_out, int out_size) {
    const float* x = (const float*)d_in[0];
    const float* sinc_w = (const float*)d_in[1];
    const float* conv1_w = (const float*)d_in[2];
    const float* conv1_b = (const float*)d_in[3];
    const float* bn1_g = (const float*)d_in[4];
    const float* bn1_b = (const float*)d_in[5];
    const float* conv2_w = (const float*)d_in[6];
    const float* conv2_b = (const float*)d_in[7];
    const float* bn2_g = (const float*)d_in[8];
    const float* bn2_b = (const float*)d_in[9];
    const float* gat1_W = (const float*)d_in[10];
    const float* gat1_asrc = (const float*)d_in[11];
    const float* gat1_adst = (const float*)d_in[12];
    const float* gat1_bias = (const float*)d_in[13];
    const float* gat2_W = (const float*)d_in[14];
    const float* gat2_asrc = (const float*)d_in[15];
    const float* gat2_adst = (const float*)d_in[16];
    const float* gat2_bias = (const float*)d_in[17];
    const float* fc1_w = (const float*)d_in[18];
    const float* fc1_b = (const float*)d_in[19];
    const float* bnf_g = (const float*)d_in[20];
    const float* bnf_b = (const float*)d_in[21];
    const float* fc2_w = (const float*)d_in[22];
    const float* fc2_b = (const float*)d_in[23];

    const int FUSED_SMEM = 23328 * 4;
    cudaFuncSetAttribute(k_fused, cudaFuncAttributeMaxDynamicSharedMemorySize, FUSED_SMEM);
    cudaFuncSetAttribute(k_att1, cudaFuncAttributeMaxDynamicSharedMemorySize, 22080 * 4);

    k_twinit<<<1, 512>>>();
    k_sinc<<<BATCH * SCC, 256>>>(x, sinc_w);
    k_stft<<<BATCH * NFR, 512>>>(x);

    dim3 gf(8, 64, BATCH);
    k_fused<<<gf, 256, FUSED_SMEM>>>(conv1_w, conv1_b, bn1_g, bn1_b,
                                     conv2_w, conv2_b, bn2_g, bn2_b);

    dim3 gg1(8, 16);
    k_gemm1_t<<<gg1, 256>>>(gat1_W);
    k_scores1<<<(BATCH * NNODES * 8 + 255) / 256, 256>>>(gat1_asrc, gat1_adst);
    k_att1<<<BATCH * 25, 256, 22080 * 4>>>(gat1_bias);

    dim3 gg2(1, 32);
    k_gemm2<<<gg2, 256>>>(gat2_W);
    k_scores2<<<(BATCH * NNODES + 255) / 256, 256>>>(gat2_asrc, gat2_adst);
    k_att2<<<BATCH, 256>>>(gat2_bias);

    int write_emb = (out_size >= 272) ? 1 : 0;
    k_head<<<BATCH, 128>>>(fc1_w, fc1_b, bnf_g, bnf_b, fc2_w, fc2_b,
                           (float*)d_out, write_emb);
}

// round 5
// speedup vs baseline: 2.4237x; 2.4237x over previous
#include <cuda_runtime.h>
#include <cstdint>

#define BATCH 8
#define TLEN 64000
#define NFR 251
#define NB 513
#define NCH 32
#define NNODES 250
#define NODE_DIM 4116
#define SCC 20
#define EPSV 1e-5f

// ---------------- scratch (device globals; no allocation) ----------------
__device__ float g_s[BATCH * NB * NFR];
__device__ float2 g_tw[512];
__device__ float g_nodes[BATCH * NNODES * NODE_DIM];
__device__ float g_gh[BATCH * NNODES * 512];
__device__ float g_ssrc[BATCH * NNODES * 8];
__device__ float g_sdst[BATCH * NNODES * 8];
__device__ float g_g1[BATCH * NNODES * 512];
__device__ float g_h2g[BATCH * NNODES * 32];
__device__ float g_s2src[BATCH * NNODES];
__device__ float g_s2dst[BATCH * NNODES];
__device__ float g_g2[BATCH * NNODES * 32];

__device__ __forceinline__ uint32_t tf32r(float x) {
    uint32_t u;
    asm("cvt.rna.tf32.f32 %0, %1;" : "=r"(u) : "f"(x));
    return u;
}
__device__ __forceinline__ void mma_tf32(float* c,
                                         uint32_t a0, uint32_t a1, uint32_t a2, uint32_t a3,
                                         uint32_t b0, uint32_t b1) {
    asm volatile("mma.sync.aligned.m16n8k8.row.col.f32.tf32.tf32.f32 "
                 "{%0,%1,%2,%3},{%4,%5,%6,%7},{%8,%9},{%0,%1,%2,%3};"
                 : "+f"(c[0]), "+f"(c[1]), "+f"(c[2]), "+f"(c[3])
                 : "r"(a0), "r"(a1), "r"(a2), "r"(a3), "r"(b0), "r"(b1));
}

// ---------------- twiddle table init ----------------
__global__ void k_twinit() {
    int t = threadIdx.x;
    float ang = -6.283185307179586f * (float)t / 1024.f;
    float si, co;
    sincosf(ang, &si, &co);
    g_tw[t] = make_float2(co, si);
}

// ---------------- sinc conv (only first 1000 outputs needed) ----------------
__global__ void k_sinc(const float* __restrict__ x, const float* __restrict__ w) {
    __shared__ float sw[1024];
    __shared__ float sx[1536];
    int b = blockIdx.x / SCC, c = blockIdx.x % SCC;
    for (int i = threadIdx.x; i < 1024; i += 256) sw[i] = w[c * 1024 + i];
    for (int i = threadIdx.x; i < 1536; i += 256)
        sx[i] = (i < 1512) ? x[b * TLEN + i] : 0.f;
    __syncthreads();
    for (int t = threadIdx.x; t < NNODES; t += 256) {
        float acc = 0.f;
        for (int q = 0; q < 4; q++) {
            int p = 4 * t + q;
            int k0 = 512 - p; if (k0 < 0) k0 = 0;
            const float* xs = sx + p - 512;
            for (int k = k0; k < 1024; k++) acc = fmaf(sw[k], xs[k], acc);
        }
        g_nodes[(b * NNODES + t) * NODE_DIM + c] = acc * 0.25f;
    }
}

// ---------------- STFT: pair-packed 1024-pt FFT (2 real frames per FFT) -----
__device__ __forceinline__ int reflect_idx(int m) {
    if (m < 0) m = -m;
    else if (m >= TLEN) m = 2 * TLEN - 2 - m;
    return m;
}
__global__ void k_stft(const float* __restrict__ x) {
    __shared__ float re[1024], im[1024];
    __shared__ float2 tw[512];
    int b = blockIdx.x / 126, p = blockIdx.x % 126;
    int t = threadIdx.x;
    tw[t] = g_tw[t];
    int fr1 = 2 * p;
    int has2 = (p < 125);
    int base1 = fr1 * 256 - 512;
    for (int n = t; n < 1024; n += 512) {
        int m1 = reflect_idx(base1 + n);
        float v1 = x[b * TLEN + m1];
        float v2 = 0.f;
        if (has2) {
            int m2 = reflect_idx(base1 + 256 + n);
            v2 = x[b * TLEN + m2];
        }
        int r = (int)(__brev((unsigned)n) >> 22);
        re[r] = v1;
        im[r] = v2;
    }
    __syncthreads();
    int mult = 512;
    for (int len = 2; len <= 1024; len <<= 1) {
        int half = len >> 1;
        int j = t & (half - 1);
        int pos = (t / half) * len + j;
        float2 wv = tw[j * mult];
        float co = wv.x, si = wv.y;
        float ur = re[pos], ui = im[pos];
        float vr = re[pos + half], vi = im[pos + half];
        float tr = vr * co - vi * si;
        float ti = vr * si + vi * co;
        re[pos] = ur + tr; im[pos] = ui + ti;
        re[pos + half] = ur - tr; im[pos + half] = ui - ti;
        mult >>= 1;
        __syncthreads();
    }
    // unpack two real spectra: X1 = (Z(k)+conj(Z(N-k)))/2, X2 = -i(Z(k)-conj(Z(N-k)))/2
    for (int k = t; k <= 512; k += 512) {        // k = t, plus t==0 handles k=512
        int kk = (k == 0 && t != 0) ? -1 : k;    // (defensive; loop gives t, then t=0 twice)
        (void)kk;
        int nk = (1024 - k) & 1023;
        float zr = re[k], zi = im[k];
        float yr = re[nk], yi = im[nk];
        float m1 = 0.5f * sqrtf((zr + yr) * (zr + yr) + (zi - yi) * (zi - yi));
        g_s[(b * NB + k) * NFR + fr1] = logf(m1 + 1e-9f);
        if (has2) {
            float m2 = 0.5f * sqrtf((zi + yi) * (zi + yi) + (yr - zr) * (yr - zr));
            g_s[(b * NB + k) * NFR + fr1 + 1] = logf(m2 + 1e-9f);
        }
    }
}

// ---------------- fused conv1 + tf32-MMA conv2 + 2x2 maxpool + scatter -------
#define H1_STRIDE 36
#define W2_STRIDE 36
__global__ void k_fused(const float* __restrict__ w1, const float* __restrict__ b1,
                        const float* __restrict__ g1v, const float* __restrict__ be1,
                        const float* __restrict__ w2, const float* __restrict__ b2,
                        const float* __restrict__ g2v, const float* __restrict__ be2) {
    extern __shared__ float smem[];
    uint32_t* h1t = (uint32_t*)smem;                 // [10][34][36] = 12240
    uint32_t* wt2 = (uint32_t*)(smem + 12240);       // [9][co=32][ci=32 pad36] = 10368
    float* sst = smem + 12240 + 10368;               // [12][36] = 432
    float* w1s = sst + 432;                          // 288
    float* pm = smem;                                // reuse: [8][32][33] = 8448

    int x0 = blockIdx.x * 32, y0 = blockIdx.y * 8, b = blockIdx.z;
    int tid = threadIdx.x;

    // load conv2 weights -> [kyx][co][ci] tf32  (transposed: conflict-free B frags)
    for (int i = tid; i < 9216; i += 256) {
        int ci = i & 31; int rest = i >> 5;
        int co = rest & 31; int kyx = rest >> 5;
        wt2[(kyx * 32 + co) * W2_STRIDE + ci] = tf32r(w2[(co * 32 + ci) * 9 + kyx]);
    }
    for (int i = tid; i < 288; i += 256) w1s[i] = w1[i];
    for (int i = tid; i < 12 * 36; i += 256) {
        int cc = i % 36, rr = i / 36;
        int gy = y0 - 2 + rr, gx = x0 - 2 + cc;
        float v = 0.f;
        if (gy >= 0 && gy < NB && gx >= 0 && gx < NFR)
            v = g_s[(b * NB + gy) * NFR + gx];
        sst[i] = v;
    }
    __syncthreads();

    // conv1 -> h1 tile [pos][ci] tf32
    {
        int ci = tid & 31;
        float cb1 = b1[ci];
        float sc1 = g1v[ci] * rsqrtf(1.f + EPSV);
        float bb1 = be1[ci];
        const float* wp = w1s + ci * 9;
        for (int r = tid >> 5; r < 340; r += 8) {
            int cc = r % 34, rr = r / 34;
            int y = y0 - 1 + rr, xg = x0 - 1 + cc;
            float v = 0.f;
            if (y >= 0 && y < NB && xg >= 0 && xg < NFR) {
                float acc = cb1;
#pragma unroll
                for (int ky = 0; ky < 3; ky++)
#pragma unroll
                    for (int kx = 0; kx < 3; kx++)
                        acc = fmaf(wp[ky * 3 + kx], sst[(rr + ky) * 36 + (cc + kx)], acc);
                acc = acc * sc1 + bb1;
                v = acc > 0.f ? acc : 0.f;
            }
            h1t[(rr * 34 + cc) * H1_STRIDE + ci] = tf32r(v);
        }
    }
    __syncthreads();

    // conv2 main loop: implicit GEMM, tf32 mma
    int warp = tid >> 5, lane = tid & 31;
    int gid = lane >> 2, tig = lane & 3;
    int yy = warp;
    float c[2][4][4] = {};
    int abase = (yy * 34 + gid) * H1_STRIDE + tig;
#pragma unroll
    for (int ky = 0; ky < 3; ky++) {
#pragma unroll
        for (int kx = 0; kx < 3; kx++) {
            int kyx = ky * 3 + kx;
            int aoff0 = abase + (ky * 34 + kx) * H1_STRIDE;
            int boff0 = (kyx * 32 + gid) * W2_STRIDE + tig;
#pragma unroll
            for (int kc = 0; kc < 4; kc++) {
                uint32_t a[2][4], bf[4][2];
#pragma unroll
                for (int mt = 0; mt < 2; mt++) {
                    int ao = aoff0 + mt * 16 * H1_STRIDE + kc * 8;
                    a[mt][0] = h1t[ao];
                    a[mt][1] = h1t[ao + 8 * H1_STRIDE];
                    a[mt][2] = h1t[ao + 4];
                    a[mt][3] = h1t[ao + 8 * H1_STRIDE + 4];
                }
#pragma unroll
                for (int nt = 0; nt < 4; nt++) {
                    int bo = boff0 + nt * 8 * W2_STRIDE + kc * 8;
                    bf[nt][0] = wt2[bo];
                    bf[nt][1] = wt2[bo + 4];
                }
#pragma unroll
                for (int mt = 0; mt < 2; mt++)
#pragma unroll
                    for (int nt = 0; nt < 4; nt++)
                        mma_tf32(c[mt][nt], a[mt][0], a[mt][1], a[mt][2], a[mt][3],
                                 bf[nt][0], bf[nt][1]);
            }
        }
    }
    __syncthreads();   // h1t dead; pm reuses it

    // epilogue: bias + BN + ReLU -> pm[y][x][co]
    float rs = rsqrtf(1.f + EPSV);
#pragma unroll
    for (int nt = 0; nt < 4; nt++) {
        int co0 = nt * 8 + tig * 2;
        float cb0 = b2[co0], sc0 = g2v[co0] * rs, bb0 = be2[co0];
        float cb1v = b2[co0 + 1], sc1v = g2v[co0 + 1] * rs, bb1v = be2[co0 + 1];
#pragma unroll
        for (int mt = 0; mt < 2; mt++) {
            int xa = mt * 16 + gid;
            int xbp = xa + 8;
            float v0 = fmaxf((c[mt][nt][0] + cb0) * sc0 + bb0, 0.f);
            float v1 = fmaxf((c[mt][nt][1] + cb1v) * sc1v + bb1v, 0.f);
            float v2 = fmaxf((c[mt][nt][2] + cb0) * sc0 + bb0, 0.f);
            float v3 = fmaxf((c[mt][nt][3] + cb1v) * sc1v + bb1v, 0.f);
            pm[(yy * 32 + xa) * 33 + co0] = v0;
            pm[(yy * 32 + xa) * 33 + co0 + 1] = v1;
            pm[(yy * 32 + xbp) * 33 + co0] = v2;
            pm[(yy * 32 + xbp) * 33 + co0 + 1] = v3;
        }
    }
    __syncthreads();

    // 2x2 maxpool + scatter float4 (4 pooled rows) into g_nodes
    int co = tid & 31, txh = tid >> 5;
#pragma unroll
    for (int t2 = 0; t2 < 2; t2++) {
        int txp = txh * 2 + t2;
        int tp = (x0 >> 1) + txp;
        if (tp < 125) {
            float4 v;
#pragma unroll
            for (int fy = 0; fy < 4; fy++) {
                int yA = 2 * fy, yB = 2 * fy + 1;
                float m0 = fmaxf(pm[(yA * 32 + 2 * txp) * 33 + co],
                                 pm[(yA * 32 + 2 * txp + 1) * 33 + co]);
                float m1 = fmaxf(pm[(yB * 32 + 2 * txp) * 33 + co],
                                 pm[(yB * 32 + 2 * txp + 1) * 33 + co]);
                ((float*)&v)[fy] = fmaxf(m0, m1);
            }
            int t = 2 * tp + (co >> 4);
            long off = (long)(b * NNODES + t) * NODE_DIM + SCC + (co & 15) * 256 + (y0 >> 1);
            *(float4*)(g_nodes + off) = v;
        }
    }
}

// ---------------- gemm1: split-tf32 (3-term), double-buffered ----------------
// C[2000,512] = nodes[2000,4116] @ W[4116,512]; 128x64 block tile, 8 warps 32x32
#define AP 20
#define BP 72
__global__ void k_gemm1_t(const float* __restrict__ Wg) {
    extern __shared__ uint32_t gsm[];
    uint32_t* Ah = gsm;                 // [2][128*20]
    uint32_t* Al = gsm + 2 * 2560;
    uint32_t* Bh = gsm + 4 * 2560;      // [2][16*72]
    uint32_t* Bl = gsm + 4 * 2560 + 2 * 1152;
    const int M = BATCH * NNODES, N = 512, K = NODE_DIM;
    const int KT = (K + 15) / 16;       // 258
    int bx = blockIdx.x, by = blockIdx.y;
    int tid = threadIdx.x;
    int warp = tid >> 5, lane = tid & 31;
    int gid = lane >> 2, tig = lane & 3;
    int wm = (warp >> 1) * 32, wn = (warp & 1) * 32;
    float c[2][4][4] = {};

    // stage tile 0 into buffer 0
#pragma unroll
    for (int j = 0; j < 8; j++) {
        int i = tid + j * 256;
        int m = i >> 4, kk = i & 15;
        int gm = by * 128 + m;
        float v = (gm < M) ? g_nodes[(long)gm * K + kk] : 0.f;
        uint32_t hi = tf32r(v);
        Ah[m * AP + kk] = hi;
        Al[m * AP + kk] = tf32r(v - __uint_as_float(hi));
    }
#pragma unroll
    for (int j = 0; j < 4; j++) {
        int i = tid + j * 256;
        int kk = i >> 6, n = i & 63;
        float v = Wg[(long)kk * N + bx * 64 + n];
        uint32_t hi = tf32r(v);
        Bh[kk * BP + n] = hi;
        Bl[kk * BP + n] = tf32r(v - __uint_as_float(hi));
    }
    __syncthreads();

    for (int kt = 0; kt < KT; kt++) {
        int buf = kt & 1;
        uint32_t* ah_ = Ah + buf * 2560;
        uint32_t* al_ = Al + buf * 2560;
        uint32_t* bh_ = Bh + buf * 1152;
        uint32_t* bl_ = Bl + buf * 1152;
        // prefetch next tile into registers
        float ra[8], rb[4];
        if (kt + 1 < KT) {
            int k0n = (kt + 1) * 16;
#pragma unroll
            for (int j = 0; j < 8; j++) {
                int i = tid + j * 256;
                int m = i >> 4, kk = i & 15;
                int gm = by * 128 + m, gk = k0n + kk;
                ra[j] = (gm < M && gk < K) ? g_nodes[(long)gm * K + gk] : 0.f;
            }
#pragma unroll
            for (int j = 0; j < 4; j++) {
                int i = tid + j * 256;
                int kk = i >> 6, n = i & 63;
                int gk = k0n + kk;
                rb[j] = (gk < K) ? Wg[(long)gk * N + bx * 64 + n] : 0.f;
            }
        }
        // mma on current buffer
#pragma unroll
        for (int ks = 0; ks < 16; ks += 8) {
            uint32_t ah[2][4], al[2][4], bh[4][2], bl[4][2];
#pragma unroll
            for (int mi = 0; mi < 2; mi++) {
                int mb = wm + mi * 16;
                int i0 = (mb + gid) * AP + ks + tig;
                int i1 = (mb + gid + 8) * AP + ks + tig;
                ah[mi][0] = ah_[i0]; ah[mi][1] = ah_[i1];
                ah[mi][2] = ah_[i0 + 4]; ah[mi][3] = ah_[i1 + 4];
                al[mi][0] = al_[i0]; al[mi][1] = al_[i1];
                al[mi][2] = al_[i0 + 4]; al[mi][3] = al_[i1 + 4];
            }
#pragma unroll
            for (int ni = 0; ni < 4; ni++) {
                int nb = wn + ni * 8;
                bh[ni][0] = bh_[(ks + tig) * BP + nb + gid];
                bh[ni][1] = bh_[(ks + tig + 4) * BP + nb + gid];
                bl[ni][0] = bl_[(ks + tig) * BP + nb + gid];
                bl[ni][1] = bl_[(ks + tig + 4) * BP + nb + gid];
            }
#pragma unroll
            for (int mi = 0; mi < 2; mi++)
#pragma unroll
                for (int ni = 0; ni < 4; ni++) {
                    mma_tf32(c[mi][ni], ah[mi][0], ah[mi][1], ah[mi][2], ah[mi][3],
                             bl[ni][0], bl[ni][1]);
                    mma_tf32(c[mi][ni], al[mi][0], al[mi][1], al[mi][2], al[mi][3],
                             bh[ni][0], bh[ni][1]);
                    mma_tf32(c[mi][ni], ah[mi][0], ah[mi][1], ah[mi][2], ah[mi][3],
                             bh[ni][0], bh[ni][1]);
                }
        }
        // store prefetched tile into other buffer
        if (kt + 1 < KT) {
            int nb2 = (kt + 1) & 1;
            uint32_t* ah2 = Ah + nb2 * 2560;
            uint32_t* al2 = Al + nb2 * 2560;
            uint32_t* bh2 = Bh + nb2 * 1152;
            uint32_t* bl2 = Bl + nb2 * 1152;
#pragma unroll
            for (int j = 0; j < 8; j++) {
                int i = tid + j * 256;
                int m = i >> 4, kk = i & 15;
                uint32_t hi = tf32r(ra[j]);
                ah2[m * AP + kk] = hi;
                al2[m * AP + kk] = tf32r(ra[j] - __uint_as_float(hi));
            }
#pragma unroll
            for (int j = 0; j < 4; j++) {
                int i = tid + j * 256;
                int kk = i >> 6, n = i & 63;
                uint32_t hi = tf32r(rb[j]);
                bh2[kk * BP + n] = hi;
                bl2[kk * BP + n] = tf32r(rb[j] - __uint_as_float(hi));
            }
        }
        __syncthreads();
    }
#pragma unroll
    for (int mi = 0; mi < 2; mi++) {
        int r0 = by * 128 + wm + mi * 16 + gid;
        int r1 = r0 + 8;
#pragma unroll
        for (int ni = 0; ni < 4; ni++) {
            int gcol = bx * 64 + wn + ni * 8 + tig * 2;
            if (r0 < M) {
                float2 v = {c[mi][ni][0], c[mi][ni][1]};
                *(float2*)(g_gh + (long)r0 * N + gcol) = v;
            }
            if (r1 < M) {
                float2 v = {c[mi][ni][2], c[mi][ni][3]};
                *(float2*)(g_gh + (long)r1 * N + gcol) = v;
            }
        }
    }
}

// ---------------- generic tiled SGEMM (64x64x16) for gemm2 -------------------
__device__ __forceinline__ void gemm_body(const float* __restrict__ A,
                                          const float* __restrict__ B,
                                          float* __restrict__ C,
                                          int M, int N, int K) {
    __shared__ float As[16][65];
    __shared__ float Bs[16][64];
    int bx = blockIdx.x, by = blockIdx.y;
    int tid = threadIdx.x;
    int tr = tid >> 4, tc = tid & 15;
    float acc[4][4] = {};
    for (int k0 = 0; k0 < K; k0 += 16) {
        for (int i = tid; i < 64 * 16; i += 256) {
            int m = i >> 4, kk = i & 15;
            int gm = by * 64 + m, gk = k0 + kk;
            As[kk][m] = (gm < M && gk < K) ? A[(long)gm * K + gk] : 0.f;
        }
        for (int i = tid; i < 16 * 64; i += 256) {
            int kk = i >> 6, n = i & 63;
            int gk = k0 + kk, gn = bx * 64 + n;
            Bs[kk][n] = (gk < K && gn < N) ? B[(long)gk * N + gn] : 0.f;
        }
        __syncthreads();
#pragma unroll
        for (int kk = 0; kk < 16; kk++) {
            float a[4], bv[4];
#pragma unroll
            for (int i = 0; i < 4; i++) a[i] = As[kk][tr * 4 + i];
#pragma unroll
            for (int jq = 0; jq < 4; jq++) bv[jq] = Bs[kk][tc * 4 + jq];
#pragma unroll
            for (int i = 0; i < 4; i++)
#pragma unroll
                for (int jq = 0; jq < 4; jq++)
                    acc[i][jq] = fmaf(a[i], bv[jq], acc[i][jq]);
        }
        __syncthreads();
    }
    for (int i = 0; i < 4; i++) {
        int gm = by * 64 + tr * 4 + i;
        if (gm >= M) continue;
        for (int jq = 0; jq < 4; jq++) {
            int gn = bx * 64 + tc * 4 + jq;
            if (gn < N) C[(long)gm * N + gn] = acc[i][jq];
        }
    }
}
__global__ void k_gemm2(const float* __restrict__ W) {
    gemm_body(g_g1, W, g_h2g, BATCH * NNODES, 32, 512);
}

// ---------------- GAT1 attention scores ----------------
__global__ void k_scores1(const float* __restrict__ asrc, const float* __restrict__ adst) {
    int idx = blockIdx.x * 256 + threadIdx.x;
    if (idx >= BATCH * NNODES * 8) return;
    int h = idx & 7;
    int bn = idx >> 3;
    const float* hp = g_gh + (long)bn * 512 + h * 64;
    float s1 = 0.f, s2 = 0.f;
    for (int f = 0; f < 64; f++) {
        float v = hp[f];
        s1 = fmaf(v, asrc[h * 64 + f], s1);
        s2 = fmaf(v, adst[h * 64 + f], s2);
    }
    g_ssrc[idx] = s1;
    g_sdst[idx] = s2;
}

// ---------------- GAT1 softmax-attention + aggregate (10 i per block) --------
__global__ void k_att1(const float* __restrict__ bias) {
    extern __shared__ float sm[];
    float* swj = sm;               // [10][250][8] = 20000
    float* ss = sm + 20000;        // 2000
    float* sums = sm + 22000;      // 80
    int b = blockIdx.x / 25, ig = blockIdx.x % 25;
    int i0 = ig * 10;
    int tid = threadIdx.x;
    for (int i = tid; i < 2000; i += 256) ss[i] = g_ssrc[b * 2000 + i];
    __syncthreads();
    int warp = tid >> 5, lane = tid & 31;
    for (int task = warp; task < 80; task += 8) {
        int ii = task >> 3, h = task & 7;
        float d = g_sdst[(b * NNODES + i0 + ii) * 8 + h];
        float mx = -1e30f;
        for (int j = lane; j < NNODES; j += 32) {
            float e = d + ss[j * 8 + h];
            e = e > 0.f ? e : 0.2f * e;
            mx = fmaxf(mx, e);
        }
#pragma unroll
        for (int o = 16; o; o >>= 1) mx = fmaxf(mx, __shfl_xor_sync(0xffffffffu, mx, o));
        float smv = 0.f;
        for (int j = lane; j < NNODES; j += 32) {
            float e = d + ss[j * 8 + h];
            e = e > 0.f ? e : 0.2f * e;
            float wv = expf(e - mx);
            swj[(ii * NNODES + j) * 8 + h] = wv;
            smv += wv;
        }
#pragma unroll
        for (int o = 16; o; o >>= 1) smv += __shfl_xor_sync(0xffffffffu, smv, o);
        if (!lane) sums[ii * 8 + h] = smv;
    }
    __syncthreads();
    float acc0[10], acc1[10];
#pragma unroll
    for (int ii = 0; ii < 10; ii++) { acc0[ii] = 0.f; acc1[ii] = 0.f; }
    const float* Hb = g_gh + (long)b * NNODES * 512;
    int f0 = tid, f1 = tid + 256;
    int h0 = f0 >> 6, h1 = f1 >> 6;
    for (int j = 0; j < NNODES; j++) {
        float v0 = Hb[j * 512 + f0];
        float v1 = Hb[j * 512 + f1];
#pragma unroll
        for (int ii = 0; ii < 10; ii++) {
            acc0[ii] = fmaf(swj[(ii * NNODES + j) * 8 + h0], v0, acc0[ii]);
            acc1[ii] = fmaf(swj[(ii * NNODES + j) * 8 + h1], v1, acc1[ii]);
        }
    }
    float bi0 = bias[f0], bi1 = bias[f1];
    for (int ii = 0; ii < 10; ii++) {
        int i = i0 + ii;
        float* op = g_g1 + (long)(b * NNODES + i) * 512;
        float o0 = acc0[ii] / sums[ii * 8 + h0] + bi0;
        float o1 = acc1[ii] / sums[ii * 8 + h1] + bi1;
        op[f0] = o0 > 0.f ? o0 : 0.f;
        op[f1] = o1 > 0.f ? o1 : 0.f;
    }
}

// ---------------- GAT2 scores ----------------
__global__ void k_scores2(const float* __restrict__ asrc, const float* __restrict__ adst) {
    int idx = blockIdx.x * 256 + threadIdx.x;
    if (idx >= BATCH * NNODES) return;
    const float* hp = g_h2g + (long)idx * 32;
    float s1 = 0.f, s2 = 0.f;
    for (int f = 0; f < 32; f++) {
        float v = hp[f];
        s1 = fmaf(v, asrc[f], s1);
        s2 = fmaf(v, adst[f], s2);
    }
    g_s2src[idx] = s1;
    g_s2dst[idx] = s2;
}

// ---------------- GAT2 attention + aggregate ----------------
__global__ void k_att2(const float* __restrict__ bias) {
    __shared__ float sh[NNODES * 32];
    __shared__ float ssr[NNODES];
    __shared__ float wjs[8][NNODES];
    int b = blockIdx.x;
    int tid = threadIdx.x, warp = tid >> 5, lane = tid & 31;
    for (int i = tid; i < NNODES * 32; i += 256) sh[i] = g_h2g[b * NNODES * 32 + i];
    for (int i = tid; i < NNODES; i += 256) ssr[i] = g_s2src[b * NNODES + i];
    __syncthreads();
    float bi = bias[lane];
    for (int i = warp; i < NNODES; i += 8) {
        float d = g_s2dst[b * NNODES + i];
        float mx = -1e30f;
        for (int j = lane; j < NNODES; j += 32) {
            float e = d + ssr[j];
            e = e > 0.f ? e : 0.2f * e;
            mx = fmaxf(mx, e);
        }
#pragma unroll
        for (int o = 16; o; o >>= 1) mx = fmaxf(mx, __shfl_xor_sync(0xffffffffu, mx, o));
        float sum = 0.f;
        for (int j = lane; j < NNODES; j += 32) {
            float e = d + ssr[j];
            e = e > 0.f ? e : 0.2f * e;
            float wv = expf(e - mx);
            wjs[warp][j] = wv;
            sum += wv;
        }
#pragma unroll
        for (int o = 16; o; o >>= 1) sum += __shfl_xor_sync(0xffffffffu, sum, o);
        __syncwarp();
        float acc = 0.f;
        for (int j = 0; j < NNODES; j++) acc = fmaf(wjs[warp][j], sh[j * 32 + lane], acc);
        g_g2[(b * NNODES + i) * 32 + lane] = acc / sum + bi;
    }
}

// ---------------- mean-pool + FC head ----------------
__global__ void k_head(const float* __restrict__ fc1w, const float* __restrict__ fc1b,
                       const float* __restrict__ bg, const float* __restrict__ bb2,
                       const float* __restrict__ fc2w, const float* __restrict__ fc2b,
                       float* __restrict__ out, int write_emb) {
    __shared__ float semb[32];
    __shared__ float sz[128];
    int b = blockIdx.x, tid = threadIdx.x;
    if (tid < 32) {
        float s = 0.f;
        for (int i = 0; i < NNODES; i++) s += g_g2[(b * NNODES + i) * 32 + tid];
        s *= (1.f / 250.f);
        semb[tid] = s;
        if (write_emb) out[16 + b * 32 + tid] = s;
    }
    __syncthreads();
    {
        float z = fc1b[tid];
        for (int f = 0; f < 32; f++) z = fmaf(semb[f], fc1w[f * 128 + tid], z);
        z = z * (bg[tid] * rsqrtf(1.f + EPSV)) + bb2[tid];
        sz[tid] = z > 0.f ? z : 0.f;
    }
    __syncthreads();
    if (tid < 2) {
        float o = fc2b[tid];
        for (int q = 0; q < 128; q++) o = fmaf(sz[q], fc2w[q * 2 + tid], o);
        out[b * 2 + tid] = o;
    }
}

extern "C" void kernel_launch(void* const* d_in, const int* in_sizes, int n_in,
                              void* d_out, int out_size) {
    const float* x = (const float*)d_in[0];
    const float* sinc_w = (const float*)d_in[1];
    const float* conv1_w = (const float*)d_in[2];
    const float* conv1_b = (const float*)d_in[3];
    const float* bn1_g = (const float*)d_in[4];
    const float* bn1_b = (const float*)d_in[5];
    const float* conv2_w = (const float*)d_in[6];
    const float* conv2_b = (const float*)d_in[7];
    const float* bn2_g = (const float*)d_in[8];
    const float* bn2_b = (const float*)d_in[9];
    const float* gat1_W = (const float*)d_in[10];
    const float* gat1_asrc = (const float*)d_in[11];
    const float* gat1_adst = (const float*)d_in[12];
    const float* gat1_bias = (const float*)d_in[13];
    const float* gat2_W = (const float*)d_in[14];
    const float* gat2_asrc = (const float*)d_in[15];
    const float* gat2_adst = (const float*)d_in[16];
    const float* gat2_bias = (const float*)d_in[17];
    const float* fc1_w = (const float*)d_in[18];
    const float* fc1_b = (const float*)d_in[19];
    const float* bnf_g = (const float*)d_in[20];
    const float* bnf_b = (const float*)d_in[21];
    const float* fc2_w = (const float*)d_in[22];
    const float* fc2_b = (const float*)d_in[23];

    const int FUSED_SMEM = 23328 * 4;
    const int GEMM1_SMEM = (4 * 2560 + 4 * 1152) * 4;   // 59392 B
    cudaFuncSetAttribute(k_fused, cudaFuncAttributeMaxDynamicSharedMemorySize, FUSED_SMEM);
    cudaFuncSetAttribute(k_gemm1_t, cudaFuncAttributeMaxDynamicSharedMemorySize, GEMM1_SMEM);
    cudaFuncSetAttribute(k_att1, cudaFuncAttributeMaxDynamicSharedMemorySize, 22080 * 4);

    k_twinit<<<1, 512>>>();
    k_sinc<<<BATCH * SCC, 256>>>(x, sinc_w);
    k_stft<<<BATCH * 126, 512>>>(x);

    dim3 gf(8, 64, BATCH);
    k_fused<<<gf, 256, FUSED_SMEM>>>(conv1_w, conv1_b, bn1_g, bn1_b,
                                     conv2_w, conv2_b, bn2_g, bn2_b);

    dim3 gg1(8, 16);
    k_gemm1_t<<<gg1, 256, GEMM1_SMEM>>>(gat1_W);
    k_scores1<<<(BATCH * NNODES * 8 + 255) / 256, 256>>>(gat1_asrc, gat1_adst);
    k_att1<<<BATCH * 25, 256, 22080 * 4>>>(gat1_bias);

    dim3 gg2(1, 32);
    k_gemm2<<<gg2, 256>>>(gat2_W);
    k_scores2<<<(BATCH * NNODES + 255) / 256, 256>>>(gat2_asrc, gat2_adst);
    k_att2<<<BATCH, 256>>>(gat2_bias);

    int write_emb = (out_size >= 272) ? 1 : 0;
    k_head<<<BATCH, 128>>>(fc1_w, fc1_b, bnf_g, bnf_b, fc2_w, fc2_b,
                           (float*)d_out, write_emb);
}